// round 1
// baseline (speedup 1.0000x reference)
#include <cuda_runtime.h>
#include <math.h>

// Problem constants
#define BATCH   32
#define NHW     64          // image height == width
#define DIM     384
#define HEADS   12
#define HD      32
#define M2      64          // tokens per window (8x8)
#define NWIN    64          // windows per image (8x8)
#define INNER   384         // HEADS*HD
#define TOK     131072      // BATCH*NHW*NHW
#define QS      50331648    // BATCH*HEADS*NWIN*M2*HD  (one qkv component)

// Scratch (device globals; no runtime allocation)
__device__ float g_qkv[3u * 50331648u];          // [qkvi][b][h][win][m2][d]
__device__ float g_bias[HEADS * M2 * M2];        // [h][i][j]
__device__ float g_attnout[(size_t)TOK * INNER]; // [b][H][W][inner], shifted coords

// ---------------------------------------------------------------------------
// CPB-MLP bias kernel: bias[h][i][j] for 12 heads, 64x64 relative positions
// ---------------------------------------------------------------------------
__global__ void __launch_bounds__(256) cpb_kernel(const float* __restrict__ w1,
                                                  const float* __restrict__ b1,
                                                  const float* __restrict__ w2,
                                                  const float* __restrict__ b2) {
    __shared__ float w1s[1024];
    __shared__ float b1s[512];
    __shared__ float w2s[6144];
    int t = threadIdx.x;
    for (int i = t; i < 1024; i += 256) w1s[i] = w1[i];
    for (int i = t; i < 512;  i += 256) b1s[i] = b1[i];
    for (int i = t; i < 6144; i += 256) w2s[i] = w2[i];
    __syncthreads();

    int idx = blockIdx.x * 256 + t;     // 0..4095 = i*64 + j
    int i = idx >> 6, j = idx & 63;
    float dx = (float)((j >> 3) - (i >> 3));   // rel = idx[j] - idx[i]
    float dy = (float)((j & 7) - (i & 7));
    float cx = (dx >= 0.f) ? log1pf(dx) : -log1pf(-dx);
    float cy = (dy >= 0.f) ? log1pf(dy) : -log1pf(-dy);

    float acc[HEADS];
#pragma unroll
    for (int h = 0; h < HEADS; h++) acc[h] = b2[h];

    for (int h0 = 0; h0 < 512; h0++) {
        float hid = fmaxf(cx * w1s[2 * h0] + cy * w1s[2 * h0 + 1] + b1s[h0], 0.f);
#pragma unroll
        for (int h = 0; h < HEADS; h++) acc[h] += hid * w2s[h * 512 + h0];
    }
#pragma unroll
    for (int h = 0; h < HEADS; h++) g_bias[h * 4096 + idx] = acc[h];
}

// ---------------------------------------------------------------------------
// GEMM 1: qkv = shifted(x) @ w_qkv^T    C[131072, 1152], K=384
// 128x128x16 tiles, 256 threads, 8x8 per-thread micro-tile.
// A gathered with cyclic shift; C scattered into g_qkv window layout.
// ---------------------------------------------------------------------------
__global__ void __launch_bounds__(256) gemm_qkv(const float* __restrict__ X,
                                                const float* __restrict__ Wq) {
    __shared__ float As[16][128];
    __shared__ float Bs[16][128];
    const int t  = threadIdx.x;
    const int bm = blockIdx.y, bn = blockIdx.x;
    const int tx = t & 15, ty = t >> 4;

    const int rowA = t >> 2;          // 0..63
    const int colL = (t & 3) * 4;     // 0,4,8,12

    // shift-gathered source offsets for rows rowA and rowA+64
    size_t aoff0, aoff1;
    {
        int m = bm * 128 + rowA;
        int b = m >> 12, rem = m & 4095;
        int H = rem >> 6, W = rem & 63;
        int Hs = (H + 4) & 63, Ws = (W + 4) & 63;
        aoff0 = (size_t)((b << 12) + (Hs << 6) + Ws) * DIM;
        m += 64;
        b = m >> 12; rem = m & 4095; H = rem >> 6; W = rem & 63;
        Hs = (H + 4) & 63; Ws = (W + 4) & 63;
        aoff1 = (size_t)((b << 12) + (Hs << 6) + Ws) * DIM;
    }
    const float* Bp0 = Wq + (size_t)(bn * 128 + rowA) * DIM + colL;
    const float* Bp1 = Bp0 + (size_t)64 * DIM;

    float acc[8][8];
#pragma unroll
    for (int i = 0; i < 8; i++)
#pragma unroll
        for (int j = 0; j < 8; j++) acc[i][j] = 0.f;

    for (int k0 = 0; k0 < DIM; k0 += 16) {
        float4 a0 = *(const float4*)(X + aoff0 + k0 + colL);
        float4 a1 = *(const float4*)(X + aoff1 + k0 + colL);
        float4 q0 = *(const float4*)(Bp0 + k0);
        float4 q1 = *(const float4*)(Bp1 + k0);
        __syncthreads();
        As[colL + 0][rowA] = a0.x; As[colL + 1][rowA] = a0.y;
        As[colL + 2][rowA] = a0.z; As[colL + 3][rowA] = a0.w;
        As[colL + 0][rowA + 64] = a1.x; As[colL + 1][rowA + 64] = a1.y;
        As[colL + 2][rowA + 64] = a1.z; As[colL + 3][rowA + 64] = a1.w;
        Bs[colL + 0][rowA] = q0.x; Bs[colL + 1][rowA] = q0.y;
        Bs[colL + 2][rowA] = q0.z; Bs[colL + 3][rowA] = q0.w;
        Bs[colL + 0][rowA + 64] = q1.x; Bs[colL + 1][rowA + 64] = q1.y;
        Bs[colL + 2][rowA + 64] = q1.z; Bs[colL + 3][rowA + 64] = q1.w;
        __syncthreads();
#pragma unroll
        for (int kk = 0; kk < 16; kk++) {
            float4 xa = *(const float4*)(&As[kk][ty * 8]);
            float4 xb = *(const float4*)(&As[kk][ty * 8 + 4]);
            float4 ya = *(const float4*)(&Bs[kk][tx * 8]);
            float4 yb = *(const float4*)(&Bs[kk][tx * 8 + 4]);
            float av[8] = {xa.x, xa.y, xa.z, xa.w, xb.x, xb.y, xb.z, xb.w};
            float bv[8] = {ya.x, ya.y, ya.z, ya.w, yb.x, yb.y, yb.z, yb.w};
#pragma unroll
            for (int i = 0; i < 8; i++)
#pragma unroll
                for (int j = 0; j < 8; j++) acc[i][j] += av[i] * bv[j];
        }
    }

    // epilogue: scatter to g_qkv[qkvi][b][h][win][m2][d]
    const int n0 = bn * 128 + tx * 8;
    const int qkvi = n0 / 384;
    const int r = n0 % 384;
    const int h = r >> 5;
    const int d0 = r & 31;          // multiple of 8 -> both float4s stay in [0,32)
#pragma unroll
    for (int i = 0; i < 8; i++) {
        int m = bm * 128 + ty * 8 + i;
        int b = m >> 12, rem = m & 4095;
        int H = rem >> 6, W = rem & 63;
        int win = ((H >> 3) << 3) + (W >> 3);
        int m2  = ((H & 7) << 3) + (W & 7);
        size_t off = ((((size_t)qkvi * BATCH + b) * HEADS + h) * 4096 + win * 64 + m2) * 32 + d0;
        float4 v0 = make_float4(acc[i][0], acc[i][1], acc[i][2], acc[i][3]);
        float4 v1 = make_float4(acc[i][4], acc[i][5], acc[i][6], acc[i][7]);
        *(float4*)(g_qkv + off)     = v0;
        *(float4*)(g_qkv + off + 4) = v1;
    }
}

// ---------------------------------------------------------------------------
// Attention kernel: one CTA per (b, h, win). 256 threads.
// ---------------------------------------------------------------------------
__global__ void __launch_bounds__(256) attn_kernel(const float* __restrict__ tau,
                                                   float* __restrict__ attn_out) {
    __shared__ __align__(16) float pool[10816];
    float* sqT = pool;           // [32][68]  q, d-major
    float* skT = pool + 2176;    // [32][68]  k, d-major
    float* svm = pool + 4352;    // [64][36]  v, row-major
    float* sp  = pool + 6656;    // [64][65]  probs
    float* so  = pool;           // [64][36]  out staging (aliases q/k, dead by then)

    const int bid = blockIdx.x;
    const int w = bid & 63;
    const int h = (bid >> 6) % HEADS;
    const int b = bid / (HEADS * NWIN);
    const int t = threadIdx.x;

    const size_t base = (((size_t)(b * HEADS + h) * NWIN + w)) * (M2 * HD);
    const float* gq = g_qkv + base;
    const float* gk = g_qkv + (size_t)QS + base;
    const float* gv = g_qkv + 2 * (size_t)QS + base;

    // load q,k transposed (d-major) and v row-major
    for (int f = t; f < 512; f += 256) {
        int m = f >> 3, d0 = (f & 7) << 2;
        float4 q4 = *(const float4*)(gq + m * 32 + d0);
        float4 k4 = *(const float4*)(gk + m * 32 + d0);
        float4 v4 = *(const float4*)(gv + m * 32 + d0);
        sqT[(d0 + 0) * 68 + m] = q4.x; sqT[(d0 + 1) * 68 + m] = q4.y;
        sqT[(d0 + 2) * 68 + m] = q4.z; sqT[(d0 + 3) * 68 + m] = q4.w;
        skT[(d0 + 0) * 68 + m] = k4.x; skT[(d0 + 1) * 68 + m] = k4.y;
        skT[(d0 + 2) * 68 + m] = k4.z; skT[(d0 + 3) * 68 + m] = k4.w;
        *(float4*)(svm + m * 36 + d0) = v4;
    }
    __syncthreads();

    // L2-normalize q and k rows (columns in the transposed layout)
    if (t < 128) {
        float* colp = (t < 64) ? sqT : skT;
        int c = t & 63;
        float ss = 0.f;
#pragma unroll
        for (int d = 0; d < 32; d++) { float v = colp[d * 68 + c]; ss += v * v; }
        float sc = 1.0f / fmaxf(sqrtf(ss), 1e-12f);
#pragma unroll
        for (int d = 0; d < 32; d++) colp[d * 68 + c] *= sc;
    }
    __syncthreads();

    // QK^T, 4x4 per thread in registers
    const int tx = t & 15, ty = t >> 4;
    const int i0 = ty * 4, j0 = tx * 4;
    float acc[4][4];
#pragma unroll
    for (int a = 0; a < 4; a++)
#pragma unroll
        for (int c = 0; c < 4; c++) acc[a][c] = 0.f;

#pragma unroll
    for (int d = 0; d < 32; d++) {
        float4 qa = *(const float4*)(sqT + d * 68 + i0);
        float4 kb = *(const float4*)(skT + d * 68 + j0);
        float qv[4] = {qa.x, qa.y, qa.z, qa.w};
        float kv[4] = {kb.x, kb.y, kb.z, kb.w};
#pragma unroll
        for (int a = 0; a < 4; a++)
#pragma unroll
            for (int c = 0; c < 4; c++) acc[a][c] += qv[a] * kv[c];
    }

    // bias + masks + softmax (row spread across 16 lanes; xor-shuffle reduce)
    const float invtau = 1.0f / fmaxf(tau[h], 0.01f);
    const bool ulm = (w >= 56);
    const bool lrm = ((w & 7) == 7);
    const float* bb = g_bias + h * 4096;

#pragma unroll
    for (int a = 0; a < 4; a++) {
        int i = i0 + a;
        float mx = -1e38f;
#pragma unroll
        for (int c = 0; c < 4; c++) {
            int j = j0 + c;
            float v = acc[a][c] * invtau + bb[i * 64 + j];
            if (ulm && (((i >= 32) ? 1 : 0) ^ ((j >= 32) ? 1 : 0))) v -= 1e30f;
            if (lrm && ((((i & 7) >= 4) ? 1 : 0) ^ (((j & 7) >= 4) ? 1 : 0))) v -= 1e30f;
            acc[a][c] = v;
            mx = fmaxf(mx, v);
        }
#pragma unroll
        for (int o = 1; o < 16; o <<= 1) mx = fmaxf(mx, __shfl_xor_sync(0xffffffffu, mx, o));
        float s = 0.f;
#pragma unroll
        for (int c = 0; c < 4; c++) {
            float e = __expf(acc[a][c] - mx);
            acc[a][c] = e;
            s += e;
        }
#pragma unroll
        for (int o = 1; o < 16; o <<= 1) s += __shfl_xor_sync(0xffffffffu, s, o);
        float inv = 1.0f / s;
#pragma unroll
        for (int c = 0; c < 4; c++) sp[i * 65 + j0 + c] = acc[a][c] * inv;
    }
    __syncthreads();

    // write attn probs to output (coalesced scalar)
    float* ag = attn_out + (size_t)bid * 4096;
    for (int idx = t; idx < 4096; idx += 256)
        ag[idx] = sp[(idx >> 6) * 65 + (idx & 63)];

    // AV: each warp owns a 4-wide d chunk; lane owns rows {lane, lane+32}
    const int lane = t & 31, wid = t >> 5;
    const int dd = wid << 2;
    float4 o0 = make_float4(0.f, 0.f, 0.f, 0.f);
    float4 o1 = make_float4(0.f, 0.f, 0.f, 0.f);
#pragma unroll
    for (int j = 0; j < 64; j++) {
        float4 v4 = *(const float4*)(svm + j * 36 + dd);
        float p0 = sp[lane * 65 + j];
        float p1 = sp[(lane + 32) * 65 + j];
        o0.x += p0 * v4.x; o0.y += p0 * v4.y; o0.z += p0 * v4.z; o0.w += p0 * v4.w;
        o1.x += p1 * v4.x; o1.y += p1 * v4.y; o1.z += p1 * v4.z; o1.w += p1 * v4.w;
    }
    // stage in smem (aliases q/k region; safe: barrier after sp-store ensures
    // all threads finished reading q/k)
    *(float4*)(so + lane * 36 + dd)        = o0;
    *(float4*)(so + (lane + 32) * 36 + dd) = o1;
    __syncthreads();

    // coalesced write to g_attnout[b][H][W][h*32+d]
    for (int f = t; f < 512; f += 256) {
        int m2 = f >> 3, d0 = (f & 7) << 2;
        int H = ((w >> 3) << 3) + (m2 >> 3);
        int W = ((w & 7) << 3) + (m2 & 7);
        size_t off = (size_t)((b << 12) + (H << 6) + W) * INNER + (h << 5) + d0;
        *(float4*)(g_attnout + off) = *(const float4*)(so + m2 * 36 + d0);
    }
}

// ---------------------------------------------------------------------------
// GEMM 2: out = attn_out @ w_out^T + b_out, inverse-roll scatter.
// C[131072, 384], K=384. Same tiling as GEMM 1.
// ---------------------------------------------------------------------------
__global__ void __launch_bounds__(256) gemm_out(const float* __restrict__ Wo,
                                                const float* __restrict__ bo,
                                                float* __restrict__ OUT) {
    __shared__ float As[16][128];
    __shared__ float Bs[16][128];
    const int t  = threadIdx.x;
    const int bm = blockIdx.y, bn = blockIdx.x;
    const int tx = t & 15, ty = t >> 4;

    const int rowA = t >> 2;
    const int colL = (t & 3) * 4;

    const float* Ap0 = g_attnout + (size_t)(bm * 128 + rowA) * INNER + colL;
    const float* Ap1 = Ap0 + (size_t)64 * INNER;
    const float* Bp0 = Wo + (size_t)(bn * 128 + rowA) * INNER + colL;
    const float* Bp1 = Bp0 + (size_t)64 * INNER;

    float acc[8][8];
#pragma unroll
    for (int i = 0; i < 8; i++)
#pragma unroll
        for (int j = 0; j < 8; j++) acc[i][j] = 0.f;

    for (int k0 = 0; k0 < INNER; k0 += 16) {
        float4 a0 = *(const float4*)(Ap0 + k0);
        float4 a1 = *(const float4*)(Ap1 + k0);
        float4 q0 = *(const float4*)(Bp0 + k0);
        float4 q1 = *(const float4*)(Bp1 + k0);
        __syncthreads();
        As[colL + 0][rowA] = a0.x; As[colL + 1][rowA] = a0.y;
        As[colL + 2][rowA] = a0.z; As[colL + 3][rowA] = a0.w;
        As[colL + 0][rowA + 64] = a1.x; As[colL + 1][rowA + 64] = a1.y;
        As[colL + 2][rowA + 64] = a1.z; As[colL + 3][rowA + 64] = a1.w;
        Bs[colL + 0][rowA] = q0.x; Bs[colL + 1][rowA] = q0.y;
        Bs[colL + 2][rowA] = q0.z; Bs[colL + 3][rowA] = q0.w;
        Bs[colL + 0][rowA + 64] = q1.x; Bs[colL + 1][rowA + 64] = q1.y;
        Bs[colL + 2][rowA + 64] = q1.z; Bs[colL + 3][rowA + 64] = q1.w;
        __syncthreads();
#pragma unroll
        for (int kk = 0; kk < 16; kk++) {
            float4 xa = *(const float4*)(&As[kk][ty * 8]);
            float4 xb = *(const float4*)(&As[kk][ty * 8 + 4]);
            float4 ya = *(const float4*)(&Bs[kk][tx * 8]);
            float4 yb = *(const float4*)(&Bs[kk][tx * 8 + 4]);
            float av[8] = {xa.x, xa.y, xa.z, xa.w, xb.x, xb.y, xb.z, xb.w};
            float bv[8] = {ya.x, ya.y, ya.z, ya.w, yb.x, yb.y, yb.z, yb.w};
#pragma unroll
            for (int i = 0; i < 8; i++)
#pragma unroll
                for (int j = 0; j < 8; j++) acc[i][j] += av[i] * bv[j];
        }
    }

    const int n0 = bn * 128 + tx * 8;
    float4 bi0 = *(const float4*)(bo + n0);
    float4 bi1 = *(const float4*)(bo + n0 + 4);
#pragma unroll
    for (int i = 0; i < 8; i++) {
        int m = bm * 128 + ty * 8 + i;
        int b = m >> 12;
        int H = (m >> 6) & 63, W = m & 63;
        int Ho = (H + 4) & 63, Wo_ = (W + 4) & 63;
        size_t off = (size_t)((b << 12) + (Ho << 6) + Wo_) * DIM + n0;
        float4 v0 = make_float4(acc[i][0] + bi0.x, acc[i][1] + bi0.y,
                                acc[i][2] + bi0.z, acc[i][3] + bi0.w);
        float4 v1 = make_float4(acc[i][4] + bi1.x, acc[i][5] + bi1.y,
                                acc[i][6] + bi1.z, acc[i][7] + bi1.w);
        *(float4*)(OUT + off)     = v0;
        *(float4*)(OUT + off + 4) = v1;
    }
}

// ---------------------------------------------------------------------------
extern "C" void kernel_launch(void* const* d_in, const int* in_sizes, int n_in,
                              void* d_out, int out_size) {
    const float* x     = (const float*)d_in[0];
    const float* w_qkv = (const float*)d_in[1];
    const float* w1    = (const float*)d_in[2];
    const float* b1    = (const float*)d_in[3];
    const float* w2    = (const float*)d_in[4];
    const float* b2    = (const float*)d_in[5];
    const float* tau   = (const float*)d_in[6];
    const float* w_out = (const float*)d_in[7];
    const float* b_out = (const float*)d_in[8];

    float* out  = (float*)d_out;                 // (32,64,64,384)
    float* attn = out + (size_t)50331648;        // (32,12,64,64,64)

    cpb_kernel<<<16, 256>>>(w1, b1, w2, b2);
    gemm_qkv<<<dim3(9, 1024), 256>>>(x, w_qkv);
    attn_kernel<<<24576, 256>>>(tau, attn);
    gemm_out<<<dim3(3, 1024), 256>>>(w_out, b_out, out);
}

// round 2
// speedup vs baseline: 3.4581x; 3.4581x over previous
#include <cuda_runtime.h>
#include <cuda_fp16.h>
#include <math.h>

// Problem constants
#define BATCH   32
#define NHW     64
#define DIM     384
#define HEADS   12
#define HD      32
#define M2      64
#define NWIN    64
#define INNER   384
#define TOK     131072
#define QS      50331648    // BATCH*HEADS*NWIN*M2*HD

// Scratch (device globals; no runtime allocation)
__device__ __half g_xh[(size_t)TOK * DIM];        // shifted x, fp16
__device__ __half g_wqh[1152 * 384];              // w_qkv fp16
__device__ __half g_woh[384 * 384];               // w_out fp16
__device__ __half g_qkvh[3ull * QS];              // [qkvi][b][h][win][m2][d] fp16
__device__ float  g_bias[HEADS * M2 * M2];        // [h][i][j]
__device__ __half g_attnh[(size_t)TOK * INNER];   // attention output, fp16, shifted coords

// ---------------------------------------------------------------------------
// mma / ldmatrix helpers
// ---------------------------------------------------------------------------
__device__ __forceinline__ void ldm4(unsigned* r, unsigned addr) {
    asm volatile("ldmatrix.sync.aligned.m8n8.x4.shared.b16 {%0,%1,%2,%3}, [%4];"
                 : "=r"(r[0]), "=r"(r[1]), "=r"(r[2]), "=r"(r[3]) : "r"(addr));
}
__device__ __forceinline__ void mma16816(float* c, const unsigned* a, unsigned b0, unsigned b1) {
    asm volatile("mma.sync.aligned.m16n8k16.row.col.f32.f16.f16.f32 "
                 "{%0,%1,%2,%3}, {%4,%5,%6,%7}, {%8,%9}, {%0,%1,%2,%3};"
                 : "+f"(c[0]), "+f"(c[1]), "+f"(c[2]), "+f"(c[3])
                 : "r"(a[0]), "r"(a[1]), "r"(a[2]), "r"(a[3]), "r"(b0), "r"(b1));
}

// ---------------------------------------------------------------------------
// shift + convert x -> g_xh (fp16, already cyclically rolled)
// ---------------------------------------------------------------------------
__global__ void __launch_bounds__(256) shiftcvt_x(const float* __restrict__ X) {
    int i4 = blockIdx.x * 256 + threadIdx.x;     // one float4 per thread
    // TOK*DIM/4 = 12582912
    int m = i4 / 96;
    int c = (i4 % 96) * 4;
    int b = m >> 12, H = (m >> 6) & 63, W = m & 63;
    int Hs = (H + 4) & 63, Ws = (W + 4) & 63;
    float4 v = *(const float4*)(X + (size_t)((b << 12) + (Hs << 6) + Ws) * DIM + c);
    __half2 h0 = __floats2half2_rn(v.x, v.y);
    __half2 h1 = __floats2half2_rn(v.z, v.w);
    uint2 out;
    out.x = *(unsigned*)&h0;
    out.y = *(unsigned*)&h1;
    *(uint2*)(g_xh + (size_t)m * DIM + c) = out;
}

// convert weights
__global__ void __launch_bounds__(256) cvt_weights(const float* __restrict__ wq,
                                                   const float* __restrict__ wo) {
    int i = blockIdx.x * 256 + threadIdx.x;
    if (i < 442368) g_wqh[i] = __float2half_rn(wq[i]);
    else if (i < 442368 + 147456) g_woh[i - 442368] = __float2half_rn(wo[i - 442368]);
}

// ---------------------------------------------------------------------------
// CPB-MLP bias kernel
// ---------------------------------------------------------------------------
__global__ void __launch_bounds__(256) cpb_kernel(const float* __restrict__ w1,
                                                  const float* __restrict__ b1,
                                                  const float* __restrict__ w2,
                                                  const float* __restrict__ b2) {
    __shared__ float w1s[1024];
    __shared__ float b1s[512];
    __shared__ float w2s[6144];
    int t = threadIdx.x;
    for (int i = t; i < 1024; i += 256) w1s[i] = w1[i];
    for (int i = t; i < 512;  i += 256) b1s[i] = b1[i];
    for (int i = t; i < 6144; i += 256) w2s[i] = w2[i];
    __syncthreads();

    int idx = blockIdx.x * 256 + t;
    int i = idx >> 6, j = idx & 63;
    float dx = (float)((j >> 3) - (i >> 3));
    float dy = (float)((j & 7) - (i & 7));
    float cx = (dx >= 0.f) ? log1pf(dx) : -log1pf(-dx);
    float cy = (dy >= 0.f) ? log1pf(dy) : -log1pf(-dy);

    float acc[HEADS];
#pragma unroll
    for (int h = 0; h < HEADS; h++) acc[h] = b2[h];
    for (int h0 = 0; h0 < 512; h0++) {
        float hid = fmaxf(cx * w1s[2 * h0] + cy * w1s[2 * h0 + 1] + b1s[h0], 0.f);
#pragma unroll
        for (int h = 0; h < HEADS; h++) acc[h] += hid * w2s[h * 512 + h0];
    }
#pragma unroll
    for (int h = 0; h < HEADS; h++) g_bias[h * 4096 + idx] = acc[h];
}

// ---------------------------------------------------------------------------
// Tensor-core GEMM 1: qkv = g_xh @ g_wqh^T  (M=131072, N=1152, K=384)
// CTA 128x128, 8 warps each 64x32, kc=64, fp16 mma, scatter epilogue -> g_qkvh
// ---------------------------------------------------------------------------
__global__ void __launch_bounds__(256) gemm_qkv_tc() {
    __shared__ __align__(16) __half As[128 * 72];
    __shared__ __align__(16) __half Bs[128 * 72];
    const int t = threadIdx.x;
    const int warp = t >> 5, lane = t & 31;
    const int wm = warp >> 2, wn = warp & 3;
    const int bm = blockIdx.y, bn = blockIdx.x;
    const int m0 = bm * 128, n0 = bn * 128;

    const unsigned sA = (unsigned)__cvta_generic_to_shared(As);
    const unsigned sB = (unsigned)__cvta_generic_to_shared(Bs);
    const int lr = lane & 15;
    const int lc = (lane >> 4) * 8;

    float acc[4][4][4];
#pragma unroll
    for (int i = 0; i < 4; i++)
#pragma unroll
        for (int j = 0; j < 4; j++)
#pragma unroll
            for (int k = 0; k < 4; k++) acc[i][j][k] = 0.f;

    for (int k0 = 0; k0 < DIM; k0 += 64) {
        uint4 ra[4], rb[4];
#pragma unroll
        for (int i = 0; i < 4; i++) {
            int c = i * 256 + t;
            int row = c >> 3, col8 = (c & 7) * 8;
            ra[i] = *(const uint4*)(g_xh + (size_t)(m0 + row) * DIM + k0 + col8);
            rb[i] = *(const uint4*)(g_wqh + (size_t)(n0 + row) * DIM + k0 + col8);
        }
        __syncthreads();
#pragma unroll
        for (int i = 0; i < 4; i++) {
            int c = i * 256 + t;
            int row = c >> 3, col8 = (c & 7) * 8;
            *(uint4*)(As + row * 72 + col8) = ra[i];
            *(uint4*)(Bs + row * 72 + col8) = rb[i];
        }
        __syncthreads();
#pragma unroll
        for (int ks = 0; ks < 4; ks++) {
            unsigned af[4][4], bf[2][4];
#pragma unroll
            for (int mt = 0; mt < 4; mt++)
                ldm4(af[mt], sA + ((wm * 64 + mt * 16 + lr) * 72 + ks * 16 + lc) * 2);
#pragma unroll
            for (int p = 0; p < 2; p++)
                ldm4(bf[p], sB + ((wn * 32 + p * 16 + lr) * 72 + ks * 16 + lc) * 2);
#pragma unroll
            for (int mt = 0; mt < 4; mt++)
#pragma unroll
                for (int nt = 0; nt < 4; nt++)
                    mma16816(acc[mt][nt], af[mt], bf[nt >> 1][nt & 1], bf[nt >> 1][(nt & 1) + 2]);
        }
    }

    // epilogue: scatter fp16 into g_qkvh[qkvi][b][h][win][m2][d]
#pragma unroll
    for (int mt = 0; mt < 4; mt++) {
#pragma unroll
        for (int nt = 0; nt < 4; nt++) {
            int col = n0 + wn * 32 + nt * 8 + (lane & 3) * 2;
            int qkvi = col / 384;
            int r = col % 384;
            int h = r >> 5, d = r & 31;
#pragma unroll
            for (int half_ = 0; half_ < 2; half_++) {
                int m = m0 + wm * 64 + mt * 16 + (lane >> 2) + half_ * 8;
                int b = m >> 12, H = (m >> 6) & 63, W = m & 63;
                int win = ((H >> 3) << 3) + (W >> 3);
                int mm = ((H & 7) << 3) + (W & 7);
                size_t off = ((((size_t)qkvi * BATCH + b) * HEADS + h) * 4096 + win * 64 + mm) * 32 + d;
                __half2 hv = __floats2half2_rn(acc[mt][nt][half_ * 2], acc[mt][nt][half_ * 2 + 1]);
                *(__half2*)(g_qkvh + off) = hv;
            }
        }
    }
}

// ---------------------------------------------------------------------------
// Attention: one CTA per (b, h, win). 256 threads. fp16 in/out, fp32 math.
// ---------------------------------------------------------------------------
__global__ void __launch_bounds__(256) attn_kernel(const float* __restrict__ tau,
                                                   float* __restrict__ attn_out) {
    __shared__ __align__(16) float pool[10816];
    float* sqT = pool;           // [32][68]
    float* skT = pool + 2176;    // [32][68]
    float* svm = pool + 4352;    // [64][36]
    float* sp  = pool + 6656;    // [64][65]
    float* so  = pool;           // [64][36] staging (aliases q/k)

    const int bid = blockIdx.x;
    const int w = bid & 63;
    const int h = (bid >> 6) % HEADS;
    const int b = bid / (HEADS * NWIN);
    const int t = threadIdx.x;

    const size_t base = (((size_t)(b * HEADS + h) * NWIN + w)) * (M2 * HD);
    const __half* gq = g_qkvh + base;
    const __half* gk = g_qkvh + (size_t)QS + base;
    const __half* gv = g_qkvh + 2 * (size_t)QS + base;

    for (int f = t; f < 512; f += 256) {
        int m = f >> 3, d0 = (f & 7) << 2;
        uint2 qr = *(const uint2*)(gq + m * 32 + d0);
        uint2 kr = *(const uint2*)(gk + m * 32 + d0);
        uint2 vr = *(const uint2*)(gv + m * 32 + d0);
        float2 q01 = __half22float2(*(__half2*)&qr.x), q23 = __half22float2(*(__half2*)&qr.y);
        float2 k01 = __half22float2(*(__half2*)&kr.x), k23 = __half22float2(*(__half2*)&kr.y);
        float2 v01 = __half22float2(*(__half2*)&vr.x), v23 = __half22float2(*(__half2*)&vr.y);
        sqT[(d0 + 0) * 68 + m] = q01.x; sqT[(d0 + 1) * 68 + m] = q01.y;
        sqT[(d0 + 2) * 68 + m] = q23.x; sqT[(d0 + 3) * 68 + m] = q23.y;
        skT[(d0 + 0) * 68 + m] = k01.x; skT[(d0 + 1) * 68 + m] = k01.y;
        skT[(d0 + 2) * 68 + m] = k23.x; skT[(d0 + 3) * 68 + m] = k23.y;
        float* vm = svm + m * 36 + d0;
        vm[0] = v01.x; vm[1] = v01.y; vm[2] = v23.x; vm[3] = v23.y;
    }
    __syncthreads();

    if (t < 128) {
        float* colp = (t < 64) ? sqT : skT;
        int c = t & 63;
        float ss = 0.f;
#pragma unroll
        for (int d = 0; d < 32; d++) { float v = colp[d * 68 + c]; ss += v * v; }
        float sc = 1.0f / fmaxf(sqrtf(ss), 1e-12f);
#pragma unroll
        for (int d = 0; d < 32; d++) colp[d * 68 + c] *= sc;
    }
    __syncthreads();

    const int tx = t & 15, ty = t >> 4;
    const int i0 = ty * 4, j0 = tx * 4;
    float acc[4][4];
#pragma unroll
    for (int a = 0; a < 4; a++)
#pragma unroll
        for (int c = 0; c < 4; c++) acc[a][c] = 0.f;

#pragma unroll
    for (int d = 0; d < 32; d++) {
        float4 qa = *(const float4*)(sqT + d * 68 + i0);
        float4 kb = *(const float4*)(skT + d * 68 + j0);
        float qv[4] = {qa.x, qa.y, qa.z, qa.w};
        float kv[4] = {kb.x, kb.y, kb.z, kb.w};
#pragma unroll
        for (int a = 0; a < 4; a++)
#pragma unroll
            for (int c = 0; c < 4; c++) acc[a][c] += qv[a] * kv[c];
    }

    const float invtau = 1.0f / fmaxf(tau[h], 0.01f);
    const bool ulm = (w >= 56);
    const bool lrm = ((w & 7) == 7);
    const float* bb = g_bias + h * 4096;

#pragma unroll
    for (int a = 0; a < 4; a++) {
        int i = i0 + a;
        float mx = -1e38f;
#pragma unroll
        for (int c = 0; c < 4; c++) {
            int j = j0 + c;
            float v = acc[a][c] * invtau + bb[i * 64 + j];
            if (ulm && (((i >= 32) ? 1 : 0) ^ ((j >= 32) ? 1 : 0))) v -= 1e30f;
            if (lrm && ((((i & 7) >= 4) ? 1 : 0) ^ (((j & 7) >= 4) ? 1 : 0))) v -= 1e30f;
            acc[a][c] = v;
            mx = fmaxf(mx, v);
        }
#pragma unroll
        for (int o = 1; o < 16; o <<= 1) mx = fmaxf(mx, __shfl_xor_sync(0xffffffffu, mx, o));
        float s = 0.f;
#pragma unroll
        for (int c = 0; c < 4; c++) {
            float e = __expf(acc[a][c] - mx);
            acc[a][c] = e;
            s += e;
        }
#pragma unroll
        for (int o = 1; o < 16; o <<= 1) s += __shfl_xor_sync(0xffffffffu, s, o);
        float inv = 1.0f / s;
#pragma unroll
        for (int c = 0; c < 4; c++) sp[i * 65 + j0 + c] = acc[a][c] * inv;
    }
    __syncthreads();

    float* ag = attn_out + (size_t)bid * 4096;
    for (int idx = t; idx < 4096; idx += 256)
        ag[idx] = sp[(idx >> 6) * 65 + (idx & 63)];

    const int lane = t & 31, wid = t >> 5;
    const int dd = wid << 2;
    float4 o0 = make_float4(0.f, 0.f, 0.f, 0.f);
    float4 o1 = make_float4(0.f, 0.f, 0.f, 0.f);
#pragma unroll
    for (int j = 0; j < 64; j++) {
        float4 v4 = *(const float4*)(svm + j * 36 + dd);
        float p0 = sp[lane * 65 + j];
        float p1 = sp[(lane + 32) * 65 + j];
        o0.x += p0 * v4.x; o0.y += p0 * v4.y; o0.z += p0 * v4.z; o0.w += p0 * v4.w;
        o1.x += p1 * v4.x; o1.y += p1 * v4.y; o1.z += p1 * v4.z; o1.w += p1 * v4.w;
    }
    *(float4*)(so + lane * 36 + dd)        = o0;
    *(float4*)(so + (lane + 32) * 36 + dd) = o1;
    __syncthreads();

    // fp16 write to g_attnh[b][H][W][h*32+d]
    for (int f = t; f < 512; f += 256) {
        int m2 = f >> 3, d0 = (f & 7) << 2;
        int H = ((w >> 3) << 3) + (m2 >> 3);
        int W = ((w & 7) << 3) + (m2 & 7);
        size_t off = (size_t)((b << 12) + (H << 6) + W) * INNER + (h << 5) + d0;
        const float* sv = so + m2 * 36 + d0;
        __half2 h0 = __floats2half2_rn(sv[0], sv[1]);
        __half2 h1 = __floats2half2_rn(sv[2], sv[3]);
        uint2 outv;
        outv.x = *(unsigned*)&h0;
        outv.y = *(unsigned*)&h1;
        *(uint2*)(g_attnh + off) = outv;
    }
}

// ---------------------------------------------------------------------------
// Tensor-core GEMM 2: out = g_attnh @ g_woh^T + b_out, inverse-roll scatter.
// M=131072, N=384, K=384
// ---------------------------------------------------------------------------
__global__ void __launch_bounds__(256) gemm_out_tc(const float* __restrict__ bo,
                                                   float* __restrict__ OUT) {
    __shared__ __align__(16) __half As[128 * 72];
    __shared__ __align__(16) __half Bs[128 * 72];
    const int t = threadIdx.x;
    const int warp = t >> 5, lane = t & 31;
    const int wm = warp >> 2, wn = warp & 3;
    const int bm = blockIdx.y, bn = blockIdx.x;
    const int m0 = bm * 128, n0 = bn * 128;

    const unsigned sA = (unsigned)__cvta_generic_to_shared(As);
    const unsigned sB = (unsigned)__cvta_generic_to_shared(Bs);
    const int lr = lane & 15;
    const int lc = (lane >> 4) * 8;

    float acc[4][4][4];
#pragma unroll
    for (int i = 0; i < 4; i++)
#pragma unroll
        for (int j = 0; j < 4; j++)
#pragma unroll
            for (int k = 0; k < 4; k++) acc[i][j][k] = 0.f;

    for (int k0 = 0; k0 < INNER; k0 += 64) {
        uint4 ra[4], rb[4];
#pragma unroll
        for (int i = 0; i < 4; i++) {
            int c = i * 256 + t;
            int row = c >> 3, col8 = (c & 7) * 8;
            ra[i] = *(const uint4*)(g_attnh + (size_t)(m0 + row) * INNER + k0 + col8);
            rb[i] = *(const uint4*)(g_woh + (size_t)(n0 + row) * INNER + k0 + col8);
        }
        __syncthreads();
#pragma unroll
        for (int i = 0; i < 4; i++) {
            int c = i * 256 + t;
            int row = c >> 3, col8 = (c & 7) * 8;
            *(uint4*)(As + row * 72 + col8) = ra[i];
            *(uint4*)(Bs + row * 72 + col8) = rb[i];
        }
        __syncthreads();
#pragma unroll
        for (int ks = 0; ks < 4; ks++) {
            unsigned af[4][4], bf[2][4];
#pragma unroll
            for (int mt = 0; mt < 4; mt++)
                ldm4(af[mt], sA + ((wm * 64 + mt * 16 + lr) * 72 + ks * 16 + lc) * 2);
#pragma unroll
            for (int p = 0; p < 2; p++)
                ldm4(bf[p], sB + ((wn * 32 + p * 16 + lr) * 72 + ks * 16 + lc) * 2);
#pragma unroll
            for (int mt = 0; mt < 4; mt++)
#pragma unroll
                for (int nt = 0; nt < 4; nt++)
                    mma16816(acc[mt][nt], af[mt], bf[nt >> 1][nt & 1], bf[nt >> 1][(nt & 1) + 2]);
        }
    }

    // epilogue: bias + inverse roll scatter (fp32)
#pragma unroll
    for (int mt = 0; mt < 4; mt++) {
#pragma unroll
        for (int nt = 0; nt < 4; nt++) {
            int col = n0 + wn * 32 + nt * 8 + (lane & 3) * 2;
            float b0 = bo[col], b1 = bo[col + 1];
#pragma unroll
            for (int half_ = 0; half_ < 2; half_++) {
                int m = m0 + wm * 64 + mt * 16 + (lane >> 2) + half_ * 8;
                int b = m >> 12, H = (m >> 6) & 63, W = m & 63;
                int Ho = (H + 4) & 63, Wo = (W + 4) & 63;
                size_t off = (size_t)((b << 12) + (Ho << 6) + Wo) * DIM + col;
                float2 v = make_float2(acc[mt][nt][half_ * 2] + b0,
                                       acc[mt][nt][half_ * 2 + 1] + b1);
                *(float2*)(OUT + off) = v;
            }
        }
    }
}

// ---------------------------------------------------------------------------
extern "C" void kernel_launch(void* const* d_in, const int* in_sizes, int n_in,
                              void* d_out, int out_size) {
    const float* x     = (const float*)d_in[0];
    const float* w_qkv = (const float*)d_in[1];
    const float* w1    = (const float*)d_in[2];
    const float* b1    = (const float*)d_in[3];
    const float* w2    = (const float*)d_in[4];
    const float* b2    = (const float*)d_in[5];
    const float* tau   = (const float*)d_in[6];
    const float* w_out = (const float*)d_in[7];
    const float* b_out = (const float*)d_in[8];

    float* out  = (float*)d_out;
    float* attn = out + (size_t)50331648;

    cpb_kernel<<<16, 256>>>(w1, b1, w2, b2);
    cvt_weights<<<2304, 256>>>(w_qkv, w_out);
    shiftcvt_x<<<49152, 256>>>(x);
    gemm_qkv_tc<<<dim3(9, 1024), 256>>>();
    attn_kernel<<<24576, 256>>>(tau, attn);
    gemm_out_tc<<<dim3(3, 1024), 256>>>(b_out, out);
}

// round 3
// speedup vs baseline: 4.6145x; 1.3344x over previous
#include <cuda_runtime.h>
#include <cuda_fp16.h>
#include <math.h>

#define BATCH   32
#define NHW     64
#define DIM     384
#define HEADS   12
#define HD      32
#define M2      64
#define NWIN    64
#define INNER   384
#define TOK     131072
#define QS      50331648ull

// Scratch
__device__ __half g_xh[(size_t)TOK * DIM];
__device__ __half g_wqh[1152 * 384];
__device__ __half g_woh[384 * 384];
__device__ __half g_qkvh[3ull * QS];
__device__ float  g_bias[HEADS * M2 * M2];
__device__ __half g_attnh[(size_t)TOK * INNER];

// ---------------------------------------------------------------------------
// helpers
// ---------------------------------------------------------------------------
__device__ __forceinline__ void ldm4(unsigned* r, unsigned addr) {
    asm volatile("ldmatrix.sync.aligned.m8n8.x4.shared.b16 {%0,%1,%2,%3}, [%4];"
                 : "=r"(r[0]), "=r"(r[1]), "=r"(r[2]), "=r"(r[3]) : "r"(addr));
}
__device__ __forceinline__ void ldm4t(unsigned* r, unsigned addr) {
    asm volatile("ldmatrix.sync.aligned.m8n8.x4.trans.shared.b16 {%0,%1,%2,%3}, [%4];"
                 : "=r"(r[0]), "=r"(r[1]), "=r"(r[2]), "=r"(r[3]) : "r"(addr));
}
__device__ __forceinline__ void mma16816(float* c, const unsigned* a, unsigned b0, unsigned b1) {
    asm volatile("mma.sync.aligned.m16n8k16.row.col.f32.f16.f16.f32 "
                 "{%0,%1,%2,%3}, {%4,%5,%6,%7}, {%8,%9}, {%0,%1,%2,%3};"
                 : "+f"(c[0]), "+f"(c[1]), "+f"(c[2]), "+f"(c[3])
                 : "r"(a[0]), "r"(a[1]), "r"(a[2]), "r"(a[3]), "r"(b0), "r"(b1));
}
__device__ __forceinline__ void cpa16(unsigned s, const void* g) {
    asm volatile("cp.async.cg.shared.global [%0], [%1], 16;" :: "r"(s), "l"(g));
}

// ---------------------------------------------------------------------------
// shift + convert x -> fp16
// ---------------------------------------------------------------------------
__global__ void __launch_bounds__(256) shiftcvt_x(const float* __restrict__ X) {
    int i4 = blockIdx.x * 256 + threadIdx.x;
    int m = i4 / 96;
    int c = (i4 % 96) * 4;
    int b = m >> 12, H = (m >> 6) & 63, W = m & 63;
    int Hs = (H + 4) & 63, Ws = (W + 4) & 63;
    float4 v = *(const float4*)(X + (size_t)((b << 12) + (Hs << 6) + Ws) * DIM + c);
    __half2 h0 = __floats2half2_rn(v.x, v.y);
    __half2 h1 = __floats2half2_rn(v.z, v.w);
    uint2 out;
    out.x = *(unsigned*)&h0;
    out.y = *(unsigned*)&h1;
    *(uint2*)(g_xh + (size_t)m * DIM + c) = out;
}

__global__ void __launch_bounds__(256) cvt_weights(const float* __restrict__ wq,
                                                   const float* __restrict__ wo) {
    int i = blockIdx.x * 256 + threadIdx.x;
    if (i < 442368) g_wqh[i] = __float2half_rn(wq[i]);
    else if (i < 442368 + 147456) g_woh[i - 442368] = __float2half_rn(wo[i - 442368]);
}

// ---------------------------------------------------------------------------
// CPB-MLP bias
// ---------------------------------------------------------------------------
__global__ void __launch_bounds__(256) cpb_kernel(const float* __restrict__ w1,
                                                  const float* __restrict__ b1,
                                                  const float* __restrict__ w2,
                                                  const float* __restrict__ b2) {
    __shared__ float w1s[1024];
    __shared__ float b1s[512];
    __shared__ float w2s[6144];
    int t = threadIdx.x;
    for (int i = t; i < 1024; i += 256) w1s[i] = w1[i];
    for (int i = t; i < 512;  i += 256) b1s[i] = b1[i];
    for (int i = t; i < 6144; i += 256) w2s[i] = w2[i];
    __syncthreads();

    int idx = blockIdx.x * 256 + t;
    int i = idx >> 6, j = idx & 63;
    float dx = (float)((j >> 3) - (i >> 3));
    float dy = (float)((j & 7) - (i & 7));
    float cx = (dx >= 0.f) ? log1pf(dx) : -log1pf(-dx);
    float cy = (dy >= 0.f) ? log1pf(dy) : -log1pf(-dy);

    float acc[HEADS];
#pragma unroll
    for (int h = 0; h < HEADS; h++) acc[h] = b2[h];
    for (int h0 = 0; h0 < 512; h0++) {
        float hid = fmaxf(cx * w1s[2 * h0] + cy * w1s[2 * h0 + 1] + b1s[h0], 0.f);
#pragma unroll
        for (int h = 0; h < HEADS; h++) acc[h] += hid * w2s[h * 512 + h0];
    }
#pragma unroll
    for (int h = 0; h < HEADS; h++) g_bias[h * 4096 + idx] = acc[h];
}

// ---------------------------------------------------------------------------
// GEMM 1: qkv = g_xh @ g_wqh^T  (M=131072, N=1152, K=384), cp.async pipelined
// ---------------------------------------------------------------------------
#define GSTAGE 9216   // 128*72 halfs per operand per stage

__global__ void __launch_bounds__(256) gemm_qkv_tc() {
    extern __shared__ __half dsm[];
    __half* As = dsm;                 // [2][128*72]
    __half* Bs = dsm + 2 * GSTAGE;    // [2][128*72]
    const int t = threadIdx.x;
    const int warp = t >> 5, lane = t & 31;
    const int wm = warp >> 2, wn = warp & 3;
    const int m0 = blockIdx.y * 128, n0 = blockIdx.x * 128;

    const unsigned sAb = (unsigned)__cvta_generic_to_shared(As);
    const unsigned sBb = (unsigned)__cvta_generic_to_shared(Bs);
    const int lr = lane & 15;
    const int lc = (lane >> 4) * 8;
    const int ldrow = t >> 3, ldcol = (t & 7) * 8;

    float acc[4][4][4];
#pragma unroll
    for (int i = 0; i < 4; i++)
#pragma unroll
        for (int j = 0; j < 4; j++)
#pragma unroll
            for (int k = 0; k < 4; k++) acc[i][j][k] = 0.f;

#define QKV_ISSUE(IT) {                                                            \
        int k0 = (IT) * 64;                                                        \
        unsigned so = ((IT) & 1) * GSTAGE * 2;                                     \
        _Pragma("unroll")                                                          \
        for (int i = 0; i < 4; i++) {                                              \
            int row = ldrow + i * 32;                                              \
            cpa16(sAb + so + (row * 72 + ldcol) * 2,                               \
                  g_xh + (size_t)(m0 + row) * DIM + k0 + ldcol);                   \
            cpa16(sBb + so + (row * 72 + ldcol) * 2,                               \
                  g_wqh + (size_t)(n0 + row) * DIM + k0 + ldcol);                  \
        }                                                                          \
        asm volatile("cp.async.commit_group;"); }

    QKV_ISSUE(0)
    for (int it = 0; it < 6; it++) {
        if (it + 1 < 6) {
            QKV_ISSUE(it + 1)
            asm volatile("cp.async.wait_group 1;");
        } else {
            asm volatile("cp.async.wait_group 0;");
        }
        __syncthreads();
        unsigned sA = sAb + (it & 1) * GSTAGE * 2;
        unsigned sB = sBb + (it & 1) * GSTAGE * 2;
#pragma unroll
        for (int ks = 0; ks < 4; ks++) {
            unsigned af[4][4], bf[2][4];
#pragma unroll
            for (int mt = 0; mt < 4; mt++)
                ldm4(af[mt], sA + ((wm * 64 + mt * 16 + lr) * 72 + ks * 16 + lc) * 2);
#pragma unroll
            for (int p = 0; p < 2; p++)
                ldm4(bf[p], sB + ((wn * 32 + p * 16 + lr) * 72 + ks * 16 + lc) * 2);
#pragma unroll
            for (int mt = 0; mt < 4; mt++)
#pragma unroll
                for (int nt = 0; nt < 4; nt++)
                    mma16816(acc[mt][nt], af[mt], bf[nt >> 1][nt & 1], bf[nt >> 1][(nt & 1) + 2]);
        }
        __syncthreads();
    }

#pragma unroll
    for (int mt = 0; mt < 4; mt++) {
#pragma unroll
        for (int nt = 0; nt < 4; nt++) {
            int col = n0 + wn * 32 + nt * 8 + (lane & 3) * 2;
            int qkvi = col / 384;
            int r = col % 384;
            int h = r >> 5, d = r & 31;
#pragma unroll
            for (int half_ = 0; half_ < 2; half_++) {
                int m = m0 + wm * 64 + mt * 16 + (lane >> 2) + half_ * 8;
                int b = m >> 12, H = (m >> 6) & 63, W = m & 63;
                int win = ((H >> 3) << 3) + (W >> 3);
                int mm = ((H & 7) << 3) + (W & 7);
                size_t off = ((((size_t)qkvi * BATCH + b) * HEADS + h) * 4096 + win * 64 + mm) * 32 + d;
                __half2 hv = __floats2half2_rn(acc[mt][nt][half_ * 2], acc[mt][nt][half_ * 2 + 1]);
                *(__half2*)(g_qkvh + off) = hv;
            }
        }
    }
}

// ---------------------------------------------------------------------------
// Tensor-core attention: one CTA (128 thr, 4 warps) per (b,h,win)
// ---------------------------------------------------------------------------
__global__ void __launch_bounds__(128) attn_tc(const float* __restrict__ tau,
                                               float* __restrict__ attn_out) {
    __shared__ __align__(16) __half sq[64 * 40];
    __shared__ __align__(16) __half sk[64 * 40];
    __shared__ __align__(16) __half sv[64 * 40];
    __shared__ __align__(16) __half sp[64 * 72];

    const int bid = blockIdx.x;
    const int w = bid & 63;
    const int h = (bid >> 6) % HEADS;
    const int b = bid / (HEADS * NWIN);
    const int t = threadIdx.x;
    const int lane = t & 31, warp = t >> 5;

    const size_t base = ((size_t)(b * HEADS + h) * NWIN + w) * 2048;
    const __half* gq = g_qkvh + base;
    const __half* gk = g_qkvh + QS + base;
    const __half* gv = g_qkvh + 2ull * QS + base;

    for (int f = t; f < 256; f += 128) {
        int row = f >> 2, ch = (f & 3) * 8;
        *(uint4*)(sq + row * 40 + ch) = *(const uint4*)(gq + row * 32 + ch);
        *(uint4*)(sk + row * 40 + ch) = *(const uint4*)(gk + row * 32 + ch);
        *(uint4*)(sv + row * 40 + ch) = *(const uint4*)(gv + row * 32 + ch);
    }
    __syncthreads();

    // L2-normalize q,k rows (thread t<64 -> q row t; t>=64 -> k row t-64)
    {
        __half* rowp = ((t < 64) ? sq : sk) + (t & 63) * 40;
        float vals[32];
        float ss = 0.f;
#pragma unroll
        for (int i = 0; i < 16; i++) {
            float2 v2 = __half22float2(*(__half2*)(rowp + 2 * i));
            vals[2 * i] = v2.x; vals[2 * i + 1] = v2.y;
            ss += v2.x * v2.x + v2.y * v2.y;
        }
        float sc = 1.f / fmaxf(sqrtf(ss), 1e-12f);
#pragma unroll
        for (int i = 0; i < 16; i++)
            *(__half2*)(rowp + 2 * i) = __floats2half2_rn(vals[2 * i] * sc, vals[2 * i + 1] * sc);
    }
    __syncthreads();

    const unsigned sqa = (unsigned)__cvta_generic_to_shared(sq);
    const unsigned ska = (unsigned)__cvta_generic_to_shared(sk);
    const unsigned sva = (unsigned)__cvta_generic_to_shared(sv);
    const unsigned spa = (unsigned)__cvta_generic_to_shared(sp);
    const int lr = lane & 15, lc = (lane >> 4) * 8;
    const int i0 = warp * 16;

    // S = q @ k^T  (16 rows per warp x 64 cols)
    float s_acc[8][4];
#pragma unroll
    for (int nt = 0; nt < 8; nt++)
#pragma unroll
        for (int c = 0; c < 4; c++) s_acc[nt][c] = 0.f;

#pragma unroll
    for (int ks = 0; ks < 2; ks++) {
        unsigned af[4], bf[4][4];
        ldm4(af, sqa + ((i0 + lr) * 40 + ks * 16 + lc) * 2);
#pragma unroll
        for (int p = 0; p < 4; p++)
            ldm4(bf[p], ska + ((p * 16 + lr) * 40 + ks * 16 + lc) * 2);
#pragma unroll
        for (int nt = 0; nt < 8; nt++)
            mma16816(s_acc[nt], af, bf[nt >> 1][nt & 1], bf[nt >> 1][(nt & 1) + 2]);
    }

    // softmax (rows r0 = i0+lane/4 and r1 = r0+8)
    const float invtau = 1.0f / fmaxf(tau[h], 0.01f);
    const bool ulm = (w >= 56);
    const bool lrm = ((w & 7) == 7);
    const float* bb = g_bias + h * 4096;
    const int r0 = i0 + (lane >> 2);
    const int r1 = r0 + 8;
    const int jb = (lane & 3) * 2;
    const bool i0ge = (r0 >= 32), i1ge = (r1 >= 32);
    const bool ih = ((r0 & 7) >= 4);   // (r1&7)==(r0&7)

    float mx0 = -1e38f, mx1 = -1e38f;
#pragma unroll
    for (int nt = 0; nt < 8; nt++) {
        int j = nt * 8 + jb;
        bool jge = (j >= 32), jh = ((j & 7) >= 4);
        float2 bv0 = *(const float2*)(bb + r0 * 64 + j);
        float2 bv1 = *(const float2*)(bb + r1 * 64 + j);
        float m0a = ((ulm && (i0ge != jge)) || (lrm && (ih != jh))) ? -1e30f : 0.f;
        float m1a = ((ulm && (i1ge != jge)) || (lrm && (ih != jh))) ? -1e30f : 0.f;
        s_acc[nt][0] = s_acc[nt][0] * invtau + bv0.x + m0a;
        s_acc[nt][1] = s_acc[nt][1] * invtau + bv0.y + m0a;
        s_acc[nt][2] = s_acc[nt][2] * invtau + bv1.x + m1a;
        s_acc[nt][3] = s_acc[nt][3] * invtau + bv1.y + m1a;
        mx0 = fmaxf(mx0, fmaxf(s_acc[nt][0], s_acc[nt][1]));
        mx1 = fmaxf(mx1, fmaxf(s_acc[nt][2], s_acc[nt][3]));
    }
    mx0 = fmaxf(mx0, __shfl_xor_sync(0xffffffffu, mx0, 1));
    mx0 = fmaxf(mx0, __shfl_xor_sync(0xffffffffu, mx0, 2));
    mx1 = fmaxf(mx1, __shfl_xor_sync(0xffffffffu, mx1, 1));
    mx1 = fmaxf(mx1, __shfl_xor_sync(0xffffffffu, mx1, 2));

    float s0 = 0.f, s1 = 0.f;
#pragma unroll
    for (int nt = 0; nt < 8; nt++) {
        s_acc[nt][0] = __expf(s_acc[nt][0] - mx0);
        s_acc[nt][1] = __expf(s_acc[nt][1] - mx0);
        s_acc[nt][2] = __expf(s_acc[nt][2] - mx1);
        s_acc[nt][3] = __expf(s_acc[nt][3] - mx1);
        s0 += s_acc[nt][0] + s_acc[nt][1];
        s1 += s_acc[nt][2] + s_acc[nt][3];
    }
    s0 += __shfl_xor_sync(0xffffffffu, s0, 1);
    s0 += __shfl_xor_sync(0xffffffffu, s0, 2);
    s1 += __shfl_xor_sync(0xffffffffu, s1, 1);
    s1 += __shfl_xor_sync(0xffffffffu, s1, 2);
    float inv0 = 1.0f / s0, inv1 = 1.0f / s1;

    float* ag = attn_out + (size_t)bid * 4096;
#pragma unroll
    for (int nt = 0; nt < 8; nt++) {
        int j = nt * 8 + jb;
        float p00 = s_acc[nt][0] * inv0, p01 = s_acc[nt][1] * inv0;
        float p10 = s_acc[nt][2] * inv1, p11 = s_acc[nt][3] * inv1;
        *(float2*)(ag + r0 * 64 + j) = make_float2(p00, p01);
        *(float2*)(ag + r1 * 64 + j) = make_float2(p10, p11);
        *(__half2*)(sp + r0 * 72 + j) = __floats2half2_rn(p00, p01);
        *(__half2*)(sp + r1 * 72 + j) = __floats2half2_rn(p10, p11);
    }
    __syncthreads();

    // O = P @ V  (16 rows per warp x 32 d)
    float o_acc[4][4];
#pragma unroll
    for (int nd = 0; nd < 4; nd++)
#pragma unroll
        for (int c = 0; c < 4; c++) o_acc[nd][c] = 0.f;

#pragma unroll
    for (int kt = 0; kt < 4; kt++) {
        unsigned af[4], bv[2][4];
        ldm4(af, spa + ((i0 + lr) * 72 + kt * 16 + lc) * 2);
#pragma unroll
        for (int ng = 0; ng < 2; ng++)
            ldm4t(bv[ng], sva + ((kt * 16 + lr) * 40 + ng * 16 + lc) * 2);
#pragma unroll
        for (int nd = 0; nd < 4; nd++) {
            int ng = nd >> 1, q = nd & 1;
            mma16816(o_acc[nd], af, bv[ng][q * 2], bv[ng][q * 2 + 1]);
        }
    }

    // epilogue: write fp16 attn-out to g_attnh[b][H][W][h*32+d]
    const int Hb = (w >> 3) << 3, Wb = (w & 7) << 3;
#pragma unroll
    for (int nd = 0; nd < 4; nd++) {
        int d = nd * 8 + jb;
        int H0 = Hb + (r0 >> 3), W0 = Wb + (r0 & 7);
        int H1 = Hb + (r1 >> 3), W1 = Wb + (r1 & 7);
        size_t off0 = (size_t)((b << 12) + (H0 << 6) + W0) * INNER + (h << 5) + d;
        size_t off1 = (size_t)((b << 12) + (H1 << 6) + W1) * INNER + (h << 5) + d;
        *(__half2*)(g_attnh + off0) = __floats2half2_rn(o_acc[nd][0], o_acc[nd][1]);
        *(__half2*)(g_attnh + off1) = __floats2half2_rn(o_acc[nd][2], o_acc[nd][3]);
    }
}

// ---------------------------------------------------------------------------
// GEMM 2: out = g_attnh @ g_woh^T + b_out (M=131072, N=384, K=384), pipelined
// ---------------------------------------------------------------------------
__global__ void __launch_bounds__(256) gemm_out_tc(const float* __restrict__ bo,
                                                   float* __restrict__ OUT) {
    extern __shared__ __half dsm[];
    __half* As = dsm;
    __half* Bs = dsm + 2 * GSTAGE;
    const int t = threadIdx.x;
    const int warp = t >> 5, lane = t & 31;
    const int wm = warp >> 2, wn = warp & 3;
    const int m0 = blockIdx.y * 128, n0 = blockIdx.x * 128;

    const unsigned sAb = (unsigned)__cvta_generic_to_shared(As);
    const unsigned sBb = (unsigned)__cvta_generic_to_shared(Bs);
    const int lr = lane & 15;
    const int lc = (lane >> 4) * 8;
    const int ldrow = t >> 3, ldcol = (t & 7) * 8;

    float acc[4][4][4];
#pragma unroll
    for (int i = 0; i < 4; i++)
#pragma unroll
        for (int j = 0; j < 4; j++)
#pragma unroll
            for (int k = 0; k < 4; k++) acc[i][j][k] = 0.f;

#define OUT_ISSUE(IT) {                                                            \
        int k0 = (IT) * 64;                                                        \
        unsigned so = ((IT) & 1) * GSTAGE * 2;                                     \
        _Pragma("unroll")                                                          \
        for (int i = 0; i < 4; i++) {                                              \
            int row = ldrow + i * 32;                                              \
            cpa16(sAb + so + (row * 72 + ldcol) * 2,                               \
                  g_attnh + (size_t)(m0 + row) * INNER + k0 + ldcol);              \
            cpa16(sBb + so + (row * 72 + ldcol) * 2,                               \
                  g_woh + (size_t)(n0 + row) * INNER + k0 + ldcol);                \
        }                                                                          \
        asm volatile("cp.async.commit_group;"); }

    OUT_ISSUE(0)
    for (int it = 0; it < 6; it++) {
        if (it + 1 < 6) {
            OUT_ISSUE(it + 1)
            asm volatile("cp.async.wait_group 1;");
        } else {
            asm volatile("cp.async.wait_group 0;");
        }
        __syncthreads();
        unsigned sA = sAb + (it & 1) * GSTAGE * 2;
        unsigned sB = sBb + (it & 1) * GSTAGE * 2;
#pragma unroll
        for (int ks = 0; ks < 4; ks++) {
            unsigned af[4][4], bf[2][4];
#pragma unroll
            for (int mt = 0; mt < 4; mt++)
                ldm4(af[mt], sA + ((wm * 64 + mt * 16 + lr) * 72 + ks * 16 + lc) * 2);
#pragma unroll
            for (int p = 0; p < 2; p++)
                ldm4(bf[p], sB + ((wn * 32 + p * 16 + lr) * 72 + ks * 16 + lc) * 2);
#pragma unroll
            for (int mt = 0; mt < 4; mt++)
#pragma unroll
                for (int nt = 0; nt < 4; nt++)
                    mma16816(acc[mt][nt], af[mt], bf[nt >> 1][nt & 1], bf[nt >> 1][(nt & 1) + 2]);
        }
        __syncthreads();
    }

#pragma unroll
    for (int mt = 0; mt < 4; mt++) {
#pragma unroll
        for (int nt = 0; nt < 4; nt++) {
            int col = n0 + wn * 32 + nt * 8 + (lane & 3) * 2;
            float b0 = bo[col], b1 = bo[col + 1];
#pragma unroll
            for (int half_ = 0; half_ < 2; half_++) {
                int m = m0 + wm * 64 + mt * 16 + (lane >> 2) + half_ * 8;
                int b = m >> 12, H = (m >> 6) & 63, W = m & 63;
                int Ho = (H + 4) & 63, Wo = (W + 4) & 63;
                size_t off = (size_t)((b << 12) + (Ho << 6) + Wo) * DIM + col;
                *(float2*)(OUT + off) = make_float2(acc[mt][nt][half_ * 2] + b0,
                                                    acc[mt][nt][half_ * 2 + 1] + b1);
            }
        }
    }
}

// ---------------------------------------------------------------------------
extern "C" void kernel_launch(void* const* d_in, const int* in_sizes, int n_in,
                              void* d_out, int out_size) {
    const float* x     = (const float*)d_in[0];
    const float* w_qkv = (const float*)d_in[1];
    const float* w1    = (const float*)d_in[2];
    const float* b1    = (const float*)d_in[3];
    const float* w2    = (const float*)d_in[4];
    const float* b2    = (const float*)d_in[5];
    const float* tau   = (const float*)d_in[6];
    const float* w_out = (const float*)d_in[7];
    const float* b_out = (const float*)d_in[8];

    float* out  = (float*)d_out;
    float* attn = out + (size_t)50331648;

    const int gemm_smem = 4 * GSTAGE * 2;   // 73728 B
    cudaFuncSetAttribute(gemm_qkv_tc, cudaFuncAttributeMaxDynamicSharedMemorySize, gemm_smem);
    cudaFuncSetAttribute(gemm_out_tc, cudaFuncAttributeMaxDynamicSharedMemorySize, gemm_smem);

    cpb_kernel<<<16, 256>>>(w1, b1, w2, b2);
    cvt_weights<<<2304, 256>>>(w_qkv, w_out);
    shiftcvt_x<<<49152, 256>>>(x);
    gemm_qkv_tc<<<dim3(9, 1024), 256, gemm_smem>>>();
    attn_tc<<<24576, 128>>>(tau, attn);
    gemm_out_tc<<<dim3(3, 1024), 256, gemm_smem>>>(b_out, out);
}